// round 3
// baseline (speedup 1.0000x reference)
#include <cuda_runtime.h>
#include <cuda_bf16.h>
#include <math.h>

// ---------------------------------------------------------------------------
// InstantNGP hash-grid embedding, 16 levels, F=2, T=2^19, 1M points.
//
// Design (round 2 — first working kernel, built for the L2 roofline):
//  * one thread per point; loop levels coarse->fine so the SM's L1 sees one
//    level's (small, hot) table region at a time; __syncthreads per level
//    keeps the block phase-aligned for L1 locality.
//  * reciprocal-multiply instead of f32 division (division would be
//    MUFU-throughput bound). Trilinear interp is continuous across cell
//    boundaries, so ulp-level floor flips are harmless.
//  * 8 independent float2 gathers per level issued back-to-back (MLP=8).
//  * accumulators in registers; final 8x STG.128 so each thread writes its
//    own full 128B output line (exact 128MB store traffic, no smem).
// ---------------------------------------------------------------------------

#define NLVL 16
#define LOG2_T 19
#define TABLE_SIZE (1u << LOG2_T)
#define HMASK (TABLE_SIZE - 1u)
#define BSZ 1048576
#define PRIME1 2654435761u
#define PRIME2 805459861u
#define TPB 256

struct LevelParams {
    float invgs;   // f32 reciprocal of f32 grid_size (host, via double)
    float resm1;   // (float)(res - 1)
};
struct AllParams {
    LevelParams lp[NLVL];
};

__global__ __launch_bounds__(TPB)
void hash_embed_kernel(const float* __restrict__ x,
                       const float* __restrict__ emb,
                       float* __restrict__ out,
                       AllParams P)
{
    const int p = blockIdx.x * TPB + threadIdx.x;   // BSZ % TPB == 0, no guard

    const float x0 = x[p * 3 + 0];
    const float x1 = x[p * 3 + 1];
    const float x2 = x[p * 3 + 2];

    float2 r[NLVL];

#pragma unroll
    for (int l = 0; l < NLVL; ++l) {
        const float invgs = P.lp[l].invgs;
        const float rm1   = P.lp[l].resm1;

        // rel = (x - GRID_MIN) / grid_size  (reciprocal-multiply variant)
        const float rel0 = (x0 + 1.0f) * invgs;
        const float rel1 = (x1 + 1.0f) * invgs;
        const float rel2 = (x2 + 1.0f) * invgs;

        float f0 = fminf(fmaxf(floorf(rel0), 0.0f), rm1);
        float f1 = fminf(fmaxf(floorf(rel1), 0.0f), rm1);
        float f2 = fminf(fmaxf(floorf(rel2), 0.0f), rm1);

        const float w0 = rel0 - f0;
        const float w1 = rel1 - f1;
        const float w2 = rel2 - f2;

        const unsigned u0 = (unsigned)f0;
        const unsigned u1 = (unsigned)f1;
        const unsigned u2 = (unsigned)f2;

        // spatial hash: dim0 prime = 1
        const unsigned a0 = u0;
        const unsigned a1 = u0 + 1u;
        const unsigned b0 = u1 * PRIME1;
        const unsigned b1 = b0 + PRIME1;
        const unsigned c0 = u2 * PRIME2;
        const unsigned c1 = c0 + PRIME2;

        const float2* __restrict__ tab =
            (const float2*)emb + (size_t)l * TABLE_SIZE;

        // 8 independent gathers (corner bit d = (k >> d) & 1)
        const unsigned h000 = (a0 ^ b0 ^ c0) & HMASK;
        const unsigned h100 = (a1 ^ b0 ^ c0) & HMASK;
        const unsigned h010 = (a0 ^ b1 ^ c0) & HMASK;
        const unsigned h110 = (a1 ^ b1 ^ c0) & HMASK;
        const unsigned h001 = (a0 ^ b0 ^ c1) & HMASK;
        const unsigned h101 = (a1 ^ b0 ^ c1) & HMASK;
        const unsigned h011 = (a0 ^ b1 ^ c1) & HMASK;
        const unsigned h111 = (a1 ^ b1 ^ c1) & HMASK;

        const float2 v000 = tab[h000];
        const float2 v100 = tab[h100];
        const float2 v010 = tab[h010];
        const float2 v110 = tab[h110];
        const float2 v001 = tab[h001];
        const float2 v101 = tab[h101];
        const float2 v011 = tab[h011];
        const float2 v111 = tab[h111];

        const float m0 = 1.0f - w0;
        const float m1 = 1.0f - w1;
        const float m2 = 1.0f - w2;

        const float p00 = m1 * m2;
        const float p10 = w1 * m2;
        const float p01 = m1 * w2;
        const float p11 = w1 * w2;

        const float wt000 = m0 * p00;
        const float wt100 = w0 * p00;
        const float wt010 = m0 * p10;
        const float wt110 = w0 * p10;
        const float wt001 = m0 * p01;
        const float wt101 = w0 * p01;
        const float wt011 = m0 * p11;
        const float wt111 = w0 * p11;

        float accx = wt000 * v000.x;
        float accy = wt000 * v000.y;
        accx = fmaf(wt100, v100.x, accx);
        accy = fmaf(wt100, v100.y, accy);
        accx = fmaf(wt010, v010.x, accx);
        accy = fmaf(wt010, v010.y, accy);
        accx = fmaf(wt110, v110.x, accx);
        accy = fmaf(wt110, v110.y, accy);
        accx = fmaf(wt001, v001.x, accx);
        accy = fmaf(wt001, v001.y, accy);
        accx = fmaf(wt101, v101.x, accx);
        accy = fmaf(wt101, v101.y, accy);
        accx = fmaf(wt011, v011.x, accx);
        accy = fmaf(wt011, v011.y, accy);
        accx = fmaf(wt111, v111.x, accx);
        accy = fmaf(wt111, v111.y, accy);

        r[l].x = accx;
        r[l].y = accy;

        // keep the block (and, statistically, the SM) on the same level so
        // L1 holds one level's hot table region at a time
        __syncthreads();
    }

    // each thread writes its own full 128-byte output line
    float4* __restrict__ o = (float4*)(out + (size_t)p * 32);
#pragma unroll
    for (int i = 0; i < 8; ++i) {
        o[i] = make_float4(r[2 * i].x, r[2 * i].y,
                           r[2 * i + 1].x, r[2 * i + 1].y);
    }
}

extern "C" void kernel_launch(void* const* d_in, const int* in_sizes, int n_in,
                              void* d_out, int out_size)
{
    const float* x   = (const float*)d_in[0];   // (1048576, 3) f32
    const float* emb = (const float*)d_in[1];   // (16, 524288, 2) f32
    float* out = (float*)d_out;                 // (1048576, 32) f32

    // Recompute RESOLUTIONS with the SAME double-precision libm formula the
    // reference uses (floor sits exactly on integer boundaries at i=3,6,9,...
    // so hardcoding risks an off-by-one vs the reference's numpy).
    AllParams P;
    const double growth = exp((log(512.0) - log(16.0)) / 15.0);
    for (int i = 0; i < NLVL; ++i) {
        int res = (int)floor(16.0 * pow(growth, (double)i));
        // grid_size as the reference's f32 sees it, then its reciprocal
        float gsf = (float)(2.0 / (double)res);
        P.lp[i].invgs = (float)(1.0 / (double)gsf);
        P.lp[i].resm1 = (float)(res - 1);
    }

    dim3 grid(BSZ / TPB);
    dim3 block(TPB);
    hash_embed_kernel<<<grid, block>>>(x, emb, out, P);
}